// round 6
// baseline (speedup 1.0000x reference)
#include <cuda_runtime.h>
#include <cstdint>

#define N_ENT 100000
#define NB    50000
#define DD    128
#define RR    8
#define EE    200000

__device__ float g_Y[(size_t)N_ENT * DD];
__device__ float g_agg[(size_t)N_ENT * DD];

// ---------------------------------------------------------------------------
// f32x2 packed helpers
// ---------------------------------------------------------------------------
__device__ __forceinline__ unsigned long long ffma2(unsigned long long a,
                                                    unsigned long long b,
                                                    unsigned long long c) {
    unsigned long long d;
    asm("fma.rn.f32x2 %0, %1, %2, %3;" : "=l"(d) : "l"(a), "l"(b), "l"(c));
    return d;
}
__device__ __forceinline__ float lo_f(unsigned long long p) {
    return __uint_as_float((unsigned int)(p & 0xffffffffull));
}
__device__ __forceinline__ float hi_f(unsigned long long p) {
    return __uint_as_float((unsigned int)(p >> 32));
}

// ---------------------------------------------------------------------------
// Zero the accumulator
// ---------------------------------------------------------------------------
__global__ void zero_kernel() {
    int n4 = N_ENT * DD / 4;
    for (int i = blockIdx.x * blockDim.x + threadIdx.x; i < n4;
         i += gridDim.x * blockDim.x)
        ((float4*)g_agg)[i] = make_float4(0.f, 0.f, 0.f, 0.f);
}

// ---------------------------------------------------------------------------
// GEMM v2 core: k-paired f32x2.  Block 256 thr, tile 128 rows x 128 cols.
// Thread: 8 rows x 8 cols; acc[r][c] holds (even-k, odd-k) partial sums.
// A pairs come from contiguous LDS.128; W pairs from a transposed, XOR-
// swizzled smem tile. Zero packing MOVs in the mainloop.
//
// Smem layout (128 KB): As[128][128] row-major, Wt transposed+swizzled:
//   element (c, k) lives at c*128 + ((k>>2 ^ (c&31))<<2) + (k&3)
// ---------------------------------------------------------------------------
#define GTILE_R 128
#define GEMM2_SMEM (2 * DD * DD * 4)   // As 64KB + Wt 64KB = 128KB

__device__ __forceinline__ void gemm2_load_tiles(
    float* As, float* Wt, const float* __restrict__ A,
    const float* __restrict__ W, int row0, int nrows, int tid)
{
    for (int idx = tid; idx < DD * 32; idx += 256) {
        int k  = idx >> 5;
        int c4 = (idx & 31) << 2;
        float4 w = ((const float4*)W)[idx];
        int kq = k >> 2, kl = k & 3;
        Wt[(c4 + 0) * DD + ((kq ^ ((c4 + 0) & 31)) << 2) + kl] = w.x;
        Wt[(c4 + 1) * DD + ((kq ^ ((c4 + 1) & 31)) << 2) + kl] = w.y;
        Wt[(c4 + 2) * DD + ((kq ^ ((c4 + 2) & 31)) << 2) + kl] = w.z;
        Wt[(c4 + 3) * DD + ((kq ^ ((c4 + 3) & 31)) << 2) + kl] = w.w;
    }
    for (int idx = tid; idx < GTILE_R * 32; idx += 256) {
        int row = idx >> 5;
        float4 v;
        if (row0 + row < nrows)
            v = ((const float4*)A)[(size_t)(row0 + row) * 32 + (idx & 31)];
        else
            v = make_float4(0.f, 0.f, 0.f, 0.f);
        ((float4*)As)[idx] = v;
    }
}

__device__ __forceinline__ void gemm2_mainloop(
    const float* As, const float* Wt, int tx, int ty,
    unsigned long long acc[8][8])
{
    const float* ap = As + ty * 8 * DD;
    #pragma unroll
    for (int i = 0; i < 8; i++)
        #pragma unroll
        for (int j = 0; j < 8; j++) acc[i][j] = 0ull;

    #pragma unroll 2
    for (int kq = 0; kq < 32; kq++) {
        ulonglong2 aq[8], wq[8];
        #pragma unroll
        for (int i = 0; i < 8; i++)
            aq[i] = *(const ulonglong2*)(ap + i * DD + kq * 4);
        #pragma unroll
        for (int j = 0; j < 8; j++) {
            int c = tx + 16 * j;
            wq[j] = *(const ulonglong2*)(Wt + c * DD + ((kq ^ (c & 31)) << 2));
        }
        #pragma unroll
        for (int i = 0; i < 8; i++)
            #pragma unroll
            for (int j = 0; j < 8; j++) {
                acc[i][j] = ffma2(aq[i].x, wq[j].x, acc[i][j]);
                acc[i][j] = ffma2(aq[i].y, wq[j].y, acc[i][j]);
            }
    }
}

__global__ void __launch_bounds__(256, 1)
gemm_y_kernel(const float* __restrict__ A, const float* __restrict__ W, int nrows)
{
    extern __shared__ float sm[];
    float* As = sm;
    float* Wt = sm + DD * DD;
    const int tid  = threadIdx.x;
    const int row0 = blockIdx.x * GTILE_R;

    gemm2_load_tiles(As, Wt, A, W, row0, nrows, tid);
    __syncthreads();

    const int tx = tid & 15;    // cols: tx + 16*j
    const int ty = tid >> 4;    // rows: ty*8 .. ty*8+7
    unsigned long long acc[8][8];
    gemm2_mainloop(As, Wt, tx, ty, acc);

    #pragma unroll
    for (int i = 0; i < 8; i++) {
        int row = row0 + ty * 8 + i;
        if (row < nrows) {
            float* yp = g_Y + (size_t)row * DD;
            #pragma unroll
            for (int j = 0; j < 8; j++) {
                int c = tx + 16 * j;
                yp[c] = lo_f(acc[i][j]) + hi_f(acc[i][j]);
            }
        }
    }
}

// ---------------------------------------------------------------------------
// Scatter: agg[src, :] += val * Y[dst, :]  (one warp/edge, float4 atomics)
// ---------------------------------------------------------------------------
__global__ void scatter_kernel(const int* __restrict__ esrc,
                               const int* __restrict__ edst,
                               const float* __restrict__ eval)
{
    int e    = (blockIdx.x * blockDim.x + threadIdx.x) >> 5;
    int lane = threadIdx.x & 31;
    if (e >= EE) return;
    int   s = __ldg(esrc + e);
    int   d = __ldg(edst + e);
    float v = __ldg(eval + e);
    float4 y = *(const float4*)(g_Y + (size_t)d * DD + lane * 4);
    float4 c = make_float4(y.x * v, y.y * v, y.z * v, y.w * v);
    atomicAdd((float4*)(g_agg + (size_t)s * DD + lane * 4), c);
}

// ---------------------------------------------------------------------------
// Epilogue v2: out[b, :] = sigmoid( A[b, :] @ W_self + agg[idx[b], :] )
// Same k-paired f32x2 mainloop as gemm v2; fused gather + sigmoid tail.
// ---------------------------------------------------------------------------
__global__ void __launch_bounds__(256, 1)
epilogue_kernel(const float* __restrict__ A, const float* __restrict__ W,
                const int* __restrict__ idx, float* __restrict__ out, int nrows)
{
    extern __shared__ float sm[];
    float* As = sm;
    float* Wt = sm + DD * DD;
    const int tid  = threadIdx.x;
    const int row0 = blockIdx.x * GTILE_R;

    gemm2_load_tiles(As, Wt, A, W, row0, nrows, tid);
    __syncthreads();

    const int tx = tid & 15;
    const int ty = tid >> 4;
    unsigned long long acc[8][8];
    gemm2_mainloop(As, Wt, tx, ty, acc);

    #pragma unroll
    for (int i = 0; i < 8; i++) {
        int row = row0 + ty * 8 + i;
        if (row < nrows) {
            int g = __ldg(idx + row);
            const float* agp = g_agg + (size_t)g * DD;
            float* op = out + (size_t)row * DD;
            #pragma unroll
            for (int j = 0; j < 8; j++) {
                int c = tx + 16 * j;
                float x = lo_f(acc[i][j]) + hi_f(acc[i][j]) + __ldg(agp + c);
                op[c] = 1.f / (1.f + __expf(-x));
            }
        }
    }
}

// ---------------------------------------------------------------------------
extern "C" void kernel_launch(void* const* d_in, const int* in_sizes, int n_in,
                              void* d_out, int out_size)
{
    const float* emb      = (const float*)d_in[0];
    const float* head_e   = (const float*)d_in[1];
    const float* tail_e   = (const float*)d_in[2];
    const float* relk     = (const float*)d_in[3];
    const float* selfk    = (const float*)d_in[4];
    const float* edge_val = (const float*)d_in[5];
    const int*   head_idx = (const int*)d_in[6];
    const int*   tail_idx = (const int*)d_in[7];
    const int*   edge_src = (const int*)d_in[8];
    const int*   edge_dst = (const int*)d_in[9];
    float*       out      = (float*)d_out;

    cudaFuncSetAttribute(gemm_y_kernel,
                         cudaFuncAttributeMaxDynamicSharedMemorySize, GEMM2_SMEM);
    cudaFuncSetAttribute(epilogue_kernel,
                         cudaFuncAttributeMaxDynamicSharedMemorySize, GEMM2_SMEM);

    zero_kernel<<<2048, 256>>>();

    const int gemm_blocks = (N_ENT + GTILE_R - 1) / GTILE_R;    // 782
    const int scat_blocks = (EE + 7) / 8;                       // 25000
    for (int r = 0; r < RR; r++) {
        gemm_y_kernel<<<gemm_blocks, 256, GEMM2_SMEM>>>(
            emb, relk + (size_t)r * DD * DD, N_ENT);
        scatter_kernel<<<scat_blocks, 256>>>(
            edge_src + (size_t)r * EE, edge_dst + (size_t)r * EE,
            edge_val + (size_t)r * EE);
    }

    const int epi_blocks = (NB + GTILE_R - 1) / GTILE_R;        // 391
    epilogue_kernel<<<epi_blocks, 256, GEMM2_SMEM>>>(
        head_e, selfk, head_idx, out, NB);
    epilogue_kernel<<<epi_blocks, 256, GEMM2_SMEM>>>(
        tail_e, selfk, tail_idx, out + (size_t)NB * DD, NB);
}